// round 4
// baseline (speedup 1.0000x reference)
#include <cuda_runtime.h>

// SharedSharedLoss: mean off-diagonal pairwise squared L2 distance / C.
// Identity: sum_{i,j} ||a_i - a_j||^2 = 2N * S2 - 2 * ||colsum||^2
// Single fused kernel: 16 column-strips x 16 row-chunks = 256 blocks x 512 thr.
// Each thread: 4 independent float4 loads (high chip-wide MLP at low regs).
// Each block reduces its strip to 32 column partials + 1 s2 partial;
// the last block to finish does the tiny final reduce (threadfence pattern).

#define N_ROWS 4096
#define N_COLS 512
#define N_COLS4 128                  // float4 groups per row
#define N_STRIPS 16                  // column strips of 32 cols (8 float4 groups)
#define N_CHUNKS 16                  // row chunks of 256 rows
#define GRID (N_STRIPS * N_CHUNKS)   // 256 blocks
#define BLK 512                      // 8 col-groups x 64 row-lanes
#define ROWS_PER_CHUNK (N_ROWS / N_CHUNKS)        // 256
#define ROW_LANES 64
#define LOADS_PER_THREAD (ROWS_PER_CHUNK / ROW_LANES)   // 4

// Deterministic scratch (no float atomics anywhere).
__device__ float g_colpart[GRID * 32];   // [rc*16+cs][32 cols] -> rc*512+col, 32 KB
__device__ float g_s2part[GRID];
__device__ unsigned int g_count = 0;     // completion counter (reset by last block)

__global__ __launch_bounds__(BLK) void fused_kernel(const float* __restrict__ A,
                                                    float* __restrict__ out) {
    const int t  = threadIdx.x;
    const int g  = t & 7;            // float4 group within strip (0..7)
    const int r0 = t >> 3;           // row lane (0..63)
    const int b  = blockIdx.x;
    const int cs = b & (N_STRIPS - 1);   // column strip
    const int rc = b >> 4;               // row chunk

    const float4* __restrict__ A4 = reinterpret_cast<const float4*>(A);

    // ---- Streaming phase: 256 rows x 32 cols per block, 4 loads/thread ----
    const int base = (rc * ROWS_PER_CHUNK + r0) * N_COLS4 + cs * 8 + g;
    float4 v0 = A4[base + 0 * ROW_LANES * N_COLS4];
    float4 v1 = A4[base + 1 * ROW_LANES * N_COLS4];
    float4 v2 = A4[base + 2 * ROW_LANES * N_COLS4];
    float4 v3 = A4[base + 3 * ROW_LANES * N_COLS4];

    float4 c = make_float4(v0.x + v1.x + v2.x + v3.x,
                           v0.y + v1.y + v2.y + v3.y,
                           v0.z + v1.z + v2.z + v3.z,
                           v0.w + v1.w + v2.w + v3.w);
    float s2 = v0.x * v0.x + v0.y * v0.y + v0.z * v0.z + v0.w * v0.w
             + v1.x * v1.x + v1.y * v1.y + v1.z * v1.z + v1.w * v1.w
             + v2.x * v2.x + v2.y * v2.y + v2.z * v2.z + v2.w * v2.w
             + v3.x * v3.x + v3.y * v3.y + v3.z * v3.z + v3.w * v3.w;

    // ---- Block reduce: colsums over the 64 row-lanes ----
    __shared__ float4 sh[BLK];
    __shared__ float warp_s2[BLK / 32];
    sh[t] = c;

    #pragma unroll
    for (int off = 16; off > 0; off >>= 1)
        s2 += __shfl_down_sync(0xFFFFFFFFu, s2, off);
    if ((t & 31) == 0) warp_s2[t >> 5] = s2;
    __syncthreads();

    // Tree-reduce sh over the r0 dimension (index = g + 8*r0).
    #pragma unroll
    for (int off = 256; off >= 8; off >>= 1) {
        if (t < off) {
            float4 o = sh[t + off];
            float4 m = sh[t];
            sh[t] = make_float4(m.x + o.x, m.y + o.y, m.z + o.z, m.w + o.w);
        }
        __syncthreads();
    }

    if (t < 8)
        reinterpret_cast<float4*>(g_colpart)[b * 8 + t] = sh[t];
    if (t == 0) {
        float tot = 0.f;
        #pragma unroll
        for (int w = 0; w < BLK / 32; w++) tot += warp_s2[w];
        g_s2part[b] = tot;
    }

    // ---- Last-block-done final reduce ----
    __threadfence();
    __syncthreads();
    __shared__ bool isLast;
    if (t == 0) {
        unsigned int old = atomicAdd(&g_count, 1u);
        isLast = (old == GRID - 1);
    }
    __syncthreads();
    if (!isLast) return;

    // Column sums: thread t (0..511) owns column t; sum its 16 chunk partials.
    // g_colpart float index = rc*512 + col — coalesced across threads.
    double dnrm = 0.0;
    {
        float s = 0.f;
        #pragma unroll
        for (int r = 0; r < N_CHUNKS; r++)
            s += g_colpart[r * N_COLS + t];
        dnrm = (double)s * (double)s;
    }
    double ds2 = (t < GRID) ? (double)g_s2part[t] : 0.0;

    // Reduce 512 doubles (16 warps) via shuffles + shared.
    __shared__ double w_nrm[BLK / 32];
    __shared__ double w_s2d[BLK / 32];
    #pragma unroll
    for (int off = 16; off > 0; off >>= 1) {
        dnrm += __shfl_down_sync(0xFFFFFFFFu, dnrm, off);
        ds2  += __shfl_down_sync(0xFFFFFFFFu, ds2, off);
    }
    if ((t & 31) == 0) { w_nrm[t >> 5] = dnrm; w_s2d[t >> 5] = ds2; }
    __syncthreads();

    if (t == 0) {
        double NS = 0.0, S2 = 0.0;
        #pragma unroll
        for (int w = 0; w < BLK / 32; w++) { NS += w_nrm[w]; S2 += w_s2d[w]; }
        const double N = (double)N_ROWS;
        const double C = (double)N_COLS;
        double total = (2.0 * N * S2 - 2.0 * NS) / C;
        out[0] = (float)(total / (N * (N - 1.0)));
        g_count = 0;   // reset for next graph replay
    }
}

extern "C" void kernel_launch(void* const* d_in, const int* in_sizes, int n_in,
                              void* d_out, int out_size) {
    const float* A = (const float*)d_in[0];
    float* out = (float*)d_out;
    (void)in_sizes; (void)n_in; (void)out_size;

    fused_kernel<<<GRID, BLK>>>(A, out);
}